// round 3
// baseline (speedup 1.0000x reference)
#include <cuda_runtime.h>
#include <math.h>

#define HH 160
#define WW 160
#define BB 4
#define CIN 64
#define COUT 64
#define KKK 9
#define PADK 4
#define HWSZ (HH*WW)
#define NPIX (BB*HH*WW)      /* 102400 */
#define EPSV 1e-5f
#define NBLK_A 100           /* 25600 threads / 256 */

// ---------------- device scratch ----------------
__device__ __align__(16) float g_off9[BB*KKK*HH*WW];
__device__ float g_partials[NBLK_A*18];
__device__ float g_scale[KKK];
__device__ float g_shift[KKK];
__device__ __align__(16) float g_wdefT[KKK*CIN*COUT];  // [k][c][o]

// ---------------- packed f32x2 helpers ----------------
__device__ __forceinline__ unsigned long long pack2(float v) {
    unsigned long long r;
    asm("mov.b64 %0, {%1, %1};" : "=l"(r) : "f"(v));
    return r;
}
__device__ __forceinline__ unsigned long long pack_pair(float a, float b) {
    unsigned long long r;
    asm("mov.b64 %0, {%1, %2};" : "=l"(r) : "f"(a), "f"(b));
    return r;
}
__device__ __forceinline__ unsigned long long fma2(unsigned long long a,
                                                   unsigned long long b,
                                                   unsigned long long c) {
    unsigned long long d;
    asm("fma.rn.f32x2 %0, %1, %2, %3;" : "=l"(d) : "l"(a), "l"(b), "l"(c));
    return d;
}
__device__ __forceinline__ float2 unpack2(unsigned long long v) {
    float2 f;
    asm("mov.b64 {%0, %1}, %2;" : "=f"(f.x), "=f"(f.y) : "l"(v));
    return f;
}

// ---------------- kernel W: transpose w_def [o][c][k] -> [k][c][o] ----------------
__global__ void transpose_wdef_kernel(const float* __restrict__ w_def) {
    int idx = blockIdx.x*256 + threadIdx.x;
    if (idx >= COUT*CIN*KKK) return;
    int o = idx/(CIN*KKK);
    int c = (idx/KKK)%CIN;
    int k = idx%KKK;
    g_wdefT[(k*CIN + c)*COUT + o] = w_def[idx];
}

// ---------------- kernel A: offset conv (9 odd channels, f32x2) + partial stats ----------------
// thread = (b, h, w4): 9 channels (padded to 10 -> 5 pairs) x 4 consecutive w.
__global__ __launch_bounds__(256) void offset_conv_kernel(
        const float* __restrict__ x,
        const float* __restrict__ w_off,
        const float* __restrict__ b_off) {
    __shared__ float wsm[576*10];   // [c*9+ky][10]: 9 odd-ch weights + 1 zero pad
    __shared__ float bo[KKK];
    __shared__ float red[8*18];

    int tid = threadIdx.x;
    for (int e = tid; e < 576*10; e += 256) {
        int j = e % 10;
        int ck = e / 10;
        wsm[e] = (j < 9) ? w_off[(2*j+1)*576 + ck] : 0.f;
    }
    if (tid < 9) bo[tid] = b_off[2*tid+1];
    __syncthreads();

    int g  = blockIdx.x*256 + tid;
    int w4 = g % 40;
    int h  = (g/40) % HH;
    int b  = g / (40*HH);

    // acc2[p][j] = (ch 2p, ch 2p+1) at w = w4*4 + j
    unsigned long long acc2[5][4];
#pragma unroll
    for (int p = 0; p < 5; p++) {
        float b0 = bo[2*p];
        float b1 = (2*p+1 < 9) ? bo[2*p+1] : 0.f;
        unsigned long long bp = pack_pair(b0, b1);
#pragma unroll
        for (int j = 0; j < 4; j++) acc2[p][j] = bp;
    }

    const float* xb = x + (size_t)b*CIN*HWSZ + w4*4;

#pragma unroll
    for (int ky = 0; ky < 9; ky++) {
        int row = h - PADK + ky;
        if ((unsigned)row >= (unsigned)HH) continue;
        const float* xr = xb + row*WW;
#pragma unroll 4
        for (int c = 0; c < CIN; c++) {
            float4 xv = *(const float4*)(xr + c*HWSZ);
            unsigned long long xp[4];
            xp[0] = pack2(xv.x); xp[1] = pack2(xv.y);
            xp[2] = pack2(xv.z); xp[3] = pack2(xv.w);
            const unsigned long long* wr =
                (const unsigned long long*)&wsm[(c*9 + ky)*10];
#pragma unroll
            for (int p = 0; p < 5; p++) {
                unsigned long long wp = wr[p];
                acc2[p][0] = fma2(wp, xp[0], acc2[p][0]);
                acc2[p][1] = fma2(wp, xp[1], acc2[p][1]);
                acc2[p][2] = fma2(wp, xp[2], acc2[p][2]);
                acc2[p][3] = fma2(wp, xp[3], acc2[p][3]);
            }
        }
    }

    // unpack, store off9, compute stats
    float ls[9], ls2[9];
#pragma unroll
    for (int jj = 0; jj < 9; jj++) { ls[jj] = 0.f; ls2[jj] = 0.f; }
#pragma unroll
    for (int p = 0; p < 5; p++) {
        float2 f[4];
#pragma unroll
        for (int j = 0; j < 4; j++) f[j] = unpack2(acc2[p][j]);
        // channel 2p
        {
            int jj = 2*p;
            float4 v = make_float4(f[0].x, f[1].x, f[2].x, f[3].x);
            *(float4*)&g_off9[((size_t)(b*9 + jj)*HH + h)*WW + w4*4] = v;
            ls[jj]  = v.x + v.y + v.z + v.w;
            ls2[jj] = v.x*v.x + v.y*v.y + v.z*v.z + v.w*v.w;
        }
        if (2*p+1 < 9) {
            int jj = 2*p+1;
            float4 v = make_float4(f[0].y, f[1].y, f[2].y, f[3].y);
            *(float4*)&g_off9[((size_t)(b*9 + jj)*HH + h)*WW + w4*4] = v;
            ls[jj]  = v.x + v.y + v.z + v.w;
            ls2[jj] = v.x*v.x + v.y*v.y + v.z*v.z + v.w*v.w;
        }
    }

#pragma unroll
    for (int off = 16; off > 0; off >>= 1) {
#pragma unroll
        for (int j = 0; j < 9; j++) {
            ls[j]  += __shfl_down_sync(0xffffffffu, ls[j],  off);
            ls2[j] += __shfl_down_sync(0xffffffffu, ls2[j], off);
        }
    }
    int lane = tid & 31, wid = tid >> 5;
    if (lane == 0) {
#pragma unroll
        for (int j = 0; j < 9; j++) {
            red[wid*18 + j]     = ls[j];
            red[wid*18 + 9 + j] = ls2[j];
        }
    }
    __syncthreads();
    if (tid < 18) {
        float s = 0.f;
#pragma unroll
        for (int i = 0; i < 8; i++) s += red[i*18 + tid];
        g_partials[blockIdx.x*18 + tid] = s;
    }
}

// ---------------- kernel B: finalize stats ----------------
__global__ void stats_kernel(const float* __restrict__ gamma,
                             const float* __restrict__ beta) {
    __shared__ float sm[18];
    int tid = threadIdx.x;
    if (tid < 18) {
        float s = 0.f;
        for (int i = 0; i < NBLK_A; i++) s += g_partials[i*18 + tid];
        sm[tid] = s;
    }
    __syncthreads();
    if (tid < 9) {
        float mean = sm[tid] * (1.0f/(float)NPIX);
        float var  = sm[9+tid] * (1.0f/(float)NPIX) - mean*mean;
        float rstd = rsqrtf(fmaxf(var, 0.f) + EPSV);
        float sc   = rstd * gamma[2*tid+1];
        g_scale[tid] = sc;
        g_shift[tid] = beta[2*tid+1] - mean*sc;
    }
}

// ---------------- kernel C: deformable conv (f32x2, 8o x 8w tile) ----------------
// Block = (h, b). Tile 64 o x 160 w. 160 threads: og=tid/20 (8 outputs), wg=tid%20.
// Thread's 8 w = {wg*2, wg*2+1} + 40*j, j=0..3 (w-pairs -> natural f32x2, LDS.64
// conflict-free: lanes 8B apart).
#define SMEM_S    0
#define SMEM_WK   (64*WW)
#define SMEM_SW0  (SMEM_WK + 64*64)
#define SMEM_SW1  (SMEM_SW0 + 9*WW)
#define SMEM_SX0  (SMEM_SW1 + 9*WW)
#define SMEM_SX1  (SMEM_SX0 + 9*WW)
#define SMEM_TOT_ELEMS (SMEM_SX1 + 9*WW)

extern __shared__ float dsm[];

__global__ __launch_bounds__(160, 2) void deform_kernel(
        const float* __restrict__ x,
        const float* __restrict__ b_def,
        float* __restrict__ out) {
    float* s   = dsm + SMEM_S;
    float* wk  = dsm + SMEM_WK;
    float* sw0 = dsm + SMEM_SW0;
    float* sw1 = dsm + SMEM_SW1;
    int*   sx0 = (int*)(dsm + SMEM_SX0);
    int*   sx1 = (int*)(dsm + SMEM_SX1);

    int tid = threadIdx.x;
    int h = blockIdx.x;
    int b = blockIdx.y;

    // ---- phase 0: offsets ----
    {
        int w = tid;  // 160 threads cover all w
        float y[9], dx[9];
#pragma unroll
        for (int k = 0; k < 9; k++) {
            float v = g_off9[((size_t)(b*9 + k)*HH + h)*WW + w];
            y[k] = tanhf(v*g_scale[k] + g_shift[k]);
        }
        dx[4] = y[4];
        float a = y[4];
#pragma unroll
        for (int k = 3; k >= 0; k--) { a += y[k]; dx[k] = a; }
        a = y[4];
#pragma unroll
        for (int k = 5; k < 9; k++) { a += y[k]; dx[k] = a; }
#pragma unroll
        for (int k = 0; k < 9; k++) {
            float px = (float)w + dx[k];
            float fl = floorf(px);
            float fx = px - fl;
            int   x0 = (int)fl;
            sw0[k*WW + w] = (x0 >= 0 && x0 < WW)       ? (1.f - fx) : 0.f;
            sw1[k*WW + w] = (x0 >= -1 && x0 < WW - 1)  ? fx         : 0.f;
            sx0[k*WW + w] = min(max(x0, 0), WW - 1);
            sx1[k*WW + w] = min(max(x0 + 1, 0), WW - 1);
        }
    }

    const int og = tid / 20;   // 0..7
    const int wg = tid % 20;   // 0..19
    const int wbase = wg*2;    // pairs at wbase + 40*j

    unsigned long long acc[8][4];
#pragma unroll
    for (int o = 0; o < 8; o++)
#pragma unroll
        for (int j = 0; j < 4; j++) acc[o][j] = 0ull;

    const float* xbatch = x + (size_t)b*CIN*HWSZ;

    for (int k = 0; k < 9; k++) {
        int row = h - PADK + k;
        if ((unsigned)row >= (unsigned)HH) continue;   // uniform across block
        __syncthreads();  // phase-0 barrier on first valid k / tile reuse barrier

        // load w_defT slice for this k (LDG latency overlaps gather below)
        {
            const float4* wsrc = (const float4*)(g_wdefT + (size_t)k*CIN*COUT);
            float4* wk4 = (float4*)wk;
#pragma unroll
            for (int i = 0; i < 7; i++) {
                int idx = tid + i*160;
                if (idx < CIN*COUT/4) wk4[idx] = wsrc[idx];
            }
        }
        // gather + interpolate samples s[c][w]; one column per thread
        {
            const float* xrow = xbatch + (size_t)row*WW;
            int oidx = k*WW + tid;
            float iw0 = sw0[oidx];
            float iw1 = sw1[oidx];
            const float* p0 = xrow + sx0[oidx];
            const float* p1 = xrow + sx1[oidx];
#pragma unroll 16
            for (int c = 0; c < CIN; c++) {
                s[c*WW + tid] = iw0*__ldg(p0 + c*HWSZ) + iw1*__ldg(p1 + c*HWSZ);
            }
        }
        __syncthreads();

        // accumulate: out[o][w] += sum_c wk[c][o] * s[c][w]
#pragma unroll 4
        for (int c = 0; c < CIN; c++) {
            const float4* wrp = (const float4*)&wk[c*COUT + og*8];
            float4 w0 = wrp[0];
            float4 w1 = wrp[1];
            unsigned long long wp[8];
            wp[0] = pack2(w0.x); wp[1] = pack2(w0.y);
            wp[2] = pack2(w0.z); wp[3] = pack2(w0.w);
            wp[4] = pack2(w1.x); wp[5] = pack2(w1.y);
            wp[6] = pack2(w1.z); wp[7] = pack2(w1.w);
            unsigned long long sv[4];
#pragma unroll
            for (int j = 0; j < 4; j++)
                sv[j] = *(const unsigned long long*)&s[c*WW + wbase + 40*j];
#pragma unroll
            for (int o = 0; o < 8; o++) {
#pragma unroll
                for (int j = 0; j < 4; j++)
                    acc[o][j] = fma2(wp[o], sv[j], acc[o][j]);
            }
        }
    }

    // epilogue
#pragma unroll
    for (int o = 0; o < 8; o++) {
        int oo = og*8 + o;
        float bv = __ldg(&b_def[oo]);
        float* orow = out + (((size_t)b*COUT + oo)*HH + h)*WW;
#pragma unroll
        for (int j = 0; j < 4; j++) {
            float2 f = unpack2(acc[o][j]);
            *(float2*)&orow[wbase + 40*j] = make_float2(f.x + bv, f.y + bv);
        }
    }
}

// ---------------- launch ----------------
extern "C" void kernel_launch(void* const* d_in, const int* in_sizes, int n_in,
                              void* d_out, int out_size) {
    const float* x     = (const float*)d_in[0];
    const float* w_off = (const float*)d_in[1];
    const float* b_off = (const float*)d_in[2];
    const float* gamma = (const float*)d_in[3];
    const float* beta  = (const float*)d_in[4];
    const float* w_def = (const float*)d_in[5];
    const float* b_def = (const float*)d_in[6];
    float* out = (float*)d_out;

    static bool attr_set = false;
    if (!attr_set) {
        cudaFuncSetAttribute(deform_kernel,
                             cudaFuncAttributeMaxDynamicSharedMemorySize,
                             SMEM_TOT_ELEMS * (int)sizeof(float));
        attr_set = true;
    }

    transpose_wdef_kernel<<<(COUT*CIN*KKK + 255)/256, 256>>>(w_def);
    offset_conv_kernel<<<NBLK_A, 256>>>(x, w_off, b_off);
    stats_kernel<<<1, 32>>>(gamma, beta);
    deform_kernel<<<dim3(HH, BB), 160, SMEM_TOT_ELEMS * (int)sizeof(float)>>>(x, b_def, out);
}